// round 1
// baseline (speedup 1.0000x reference)
#include <cuda_runtime.h>
#include <math.h>

#define S_LEN 2048
#define HID 1024
#define NH 16
#define HD 64
#define WIN_HALF 512
#define GSTRIDE 512

// Scratch (device globals; no allocation in kernel_launch)
__device__ float g_q[S_LEN * HID];
__device__ float g_k[S_LEN * HID];
__device__ float g_v[S_LEN * HID];
__device__ float g_att[S_LEN * HID];

// ---------------------------------------------------------------------------
// Tiled SGEMM: C[M,N] = A[M,K] * B[K,N], fp32. BM=BN=64, BK=16, 16x16 threads,
// each thread computes a 4x4 micro-tile. A tile stored transposed in smem.
// ---------------------------------------------------------------------------
#define BM 64
#define BN 64
#define BK 16

__global__ __launch_bounds__(256) void gemm_kernel(const float* __restrict__ A,
                                                   const float* __restrict__ B,
                                                   float* __restrict__ C,
                                                   int M, int N, int K) {
    __shared__ float As[BK][BM];      // transposed A tile
    __shared__ float Bs[BK][BN];

    const int tx = threadIdx.x;       // 0..15
    const int ty = threadIdx.y;       // 0..15
    const int tid = ty * 16 + tx;
    const int row0 = blockIdx.y * BM;
    const int col0 = blockIdx.x * BN;

    float acc[4][4] = {};

    for (int k0 = 0; k0 < K; k0 += BK) {
        // Load A tile 64x16: one float4 per thread, store transposed
        {
            int r = tid >> 2;              // 0..63
            int c = (tid & 3) * 4;         // 0,4,8,12
            float4 av = *(const float4*)(A + (size_t)(row0 + r) * K + k0 + c);
            As[c + 0][r] = av.x;
            As[c + 1][r] = av.y;
            As[c + 2][r] = av.z;
            As[c + 3][r] = av.w;
        }
        // Load B tile 16x64: one float4 per thread
        {
            int r = tid >> 4;              // 0..15
            int c = (tid & 15) * 4;        // 0..60
            float4 bv = *(const float4*)(B + (size_t)(k0 + r) * N + col0 + c);
            *(float4*)&Bs[r][c] = bv;
        }
        __syncthreads();

#pragma unroll
        for (int kk = 0; kk < BK; kk++) {
            float4 a4 = *(const float4*)&As[kk][ty * 4];
            float4 b4 = *(const float4*)&Bs[kk][tx * 4];
            float a[4] = {a4.x, a4.y, a4.z, a4.w};
            float b[4] = {b4.x, b4.y, b4.z, b4.w};
#pragma unroll
            for (int x = 0; x < 4; x++)
#pragma unroll
                for (int y = 0; y < 4; y++)
                    acc[x][y] += a[x] * b[y];
        }
        __syncthreads();
    }

#pragma unroll
    for (int x = 0; x < 4; x++) {
        float* crow = C + (size_t)(row0 + ty * 4 + x) * N + col0 + tx * 4;
        float4 v = make_float4(acc[x][0], acc[x][1], acc[x][2], acc[x][3]);
        *(float4*)crow = v;
    }
}

// ---------------------------------------------------------------------------
// Sparse attention: one block per (query i, head h).
// Key set: globals {0,512,1024,1536} with j < lo, plus window [lo, i],
// lo = max(0, i-512). All keys are unmasked (no -inf handling needed).
// ---------------------------------------------------------------------------
#define ATT_THREADS 128
#define MAX_KEYS 544

__global__ __launch_bounds__(ATT_THREADS) void attn_kernel(const float* __restrict__ q,
                                                           const float* __restrict__ k,
                                                           const float* __restrict__ v,
                                                           float* __restrict__ out) {
    const int i = blockIdx.x;
    const int h = blockIdx.y;
    const int tid = threadIdx.x;

    __shared__ float qs[HD];
    __shared__ float sc[MAX_KEYS];
    __shared__ float red[ATT_THREADS];

    const float* qrow = q + (size_t)i * HID + h * HD;
    if (tid < HD) qs[tid] = qrow[tid];
    __syncthreads();

    const int lo = max(0, i - WIN_HALF);
    const int n_glob = (lo + GSTRIDE - 1) / GSTRIDE;  // globals strictly below lo
    const int n_keys = n_glob + (i - lo + 1);

    // Phase 1: scores
    for (int t = tid; t < n_keys; t += ATT_THREADS) {
        int j = (t < n_glob) ? (t * GSTRIDE) : (lo + t - n_glob);
        const float* krow = k + (size_t)j * HID + h * HD;
        float s = 0.f;
#pragma unroll
        for (int d = 0; d < HD; d++) s += qs[d] * krow[d];
        sc[t] = s * 0.125f;  // 1/sqrt(64)
    }
    __syncthreads();

    // Phase 2a: block max
    float m = -1e30f;
    for (int t = tid; t < n_keys; t += ATT_THREADS) m = fmaxf(m, sc[t]);
    red[tid] = m;
    __syncthreads();
    for (int s = ATT_THREADS / 2; s > 0; s >>= 1) {
        if (tid < s) red[tid] = fmaxf(red[tid], red[tid + s]);
        __syncthreads();
    }
    const float mx = red[0];
    __syncthreads();

    // Phase 2b: exp + block sum
    float lsum = 0.f;
    for (int t = tid; t < n_keys; t += ATT_THREADS) {
        float e = expf(sc[t] - mx);
        sc[t] = e;
        lsum += e;
    }
    red[tid] = lsum;
    __syncthreads();
    for (int s = ATT_THREADS / 2; s > 0; s >>= 1) {
        if (tid < s) red[tid] += red[tid + s];
        __syncthreads();
    }
    const float inv = 1.0f / red[0];
    __syncthreads();

    // Phase 3: out[d] = sum_t p[t] * V[j(t)][d], split keys into 2 halves
    const int d = tid & (HD - 1);
    const int half = tid >> 6;  // 0 or 1
    float acc = 0.f;
    for (int t = half; t < n_keys; t += 2) {
        int j = (t < n_glob) ? (t * GSTRIDE) : (lo + t - n_glob);
        acc += sc[t] * v[(size_t)j * HID + h * HD + d];
    }
    red[tid] = acc;
    __syncthreads();
    if (tid < HD) {
        out[(size_t)i * HID + h * HD + tid] = (red[tid] + red[tid + HD]) * inv;
    }
}

// ---------------------------------------------------------------------------
extern "C" void kernel_launch(void* const* d_in, const int* in_sizes, int n_in,
                              void* d_out, int out_size) {
    const float* x   = (const float*)d_in[0];  // [1, 2048, 1024]
    const float* w_q = (const float*)d_in[1];  // [1024, 1024]
    const float* w_k = (const float*)d_in[2];
    const float* w_v = (const float*)d_in[3];
    const float* w_o = (const float*)d_in[4];
    float* out = (float*)d_out;                // [1, 2048, 1024]

    float *q, *k, *v, *att;
    cudaGetSymbolAddress((void**)&q, g_q);
    cudaGetSymbolAddress((void**)&k, g_k);
    cudaGetSymbolAddress((void**)&v, g_v);
    cudaGetSymbolAddress((void**)&att, g_att);

    dim3 gblock(16, 16);
    dim3 ggrid(HID / BN, S_LEN / BM);  // (16, 32)

    gemm_kernel<<<ggrid, gblock>>>(x, w_q, q, S_LEN, HID, HID);
    gemm_kernel<<<ggrid, gblock>>>(x, w_k, k, S_LEN, HID, HID);
    gemm_kernel<<<ggrid, gblock>>>(x, w_v, v, S_LEN, HID, HID);

    dim3 agrid(S_LEN, NH);
    attn_kernel<<<agrid, ATT_THREADS>>>(q, k, v, att);

    gemm_kernel<<<ggrid, gblock>>>(att, w_o, out, S_LEN, HID, HID);
}

// round 2
// speedup vs baseline: 6.4046x; 6.4046x over previous
#include <cuda_runtime.h>
#include <math.h>

#define S_LEN 2048
#define HID 1024
#define NH 16
#define HD 64

// Scratch (device globals; no allocation in kernel_launch)
__device__ float g_q[S_LEN * HID];
__device__ float g_k[S_LEN * HID];
__device__ float g_v[S_LEN * HID];
__device__ float g_att[S_LEN * HID];

// ---------------------------------------------------------------------------
// SGEMM: C[M,N] = A[M,K]*B[K,N]. 128x128 tile, BK=16, 256 threads, 8x8 micro,
// register-prefetch double buffering.
// ---------------------------------------------------------------------------
#define GBK 16

__global__ __launch_bounds__(256) void gemm_kernel(const float* __restrict__ A,
                                                   const float* __restrict__ B,
                                                   float* __restrict__ C,
                                                   int M, int N, int K) {
    __shared__ float As[GBK][132];   // transposed A tile, padded
    __shared__ float Bs[GBK][128];

    const int tid = threadIdx.x;
    const int tx = tid & 15;
    const int ty = tid >> 4;
    const int row0 = blockIdx.y * 128;
    const int col0 = blockIdx.x * 128;

    float4 ar[2], br[2];
    float acc[8][8] = {};

    const int ntiles = K >> 4;

    // --- load tile 0 into regs ---
#pragma unroll
    for (int l = 0; l < 2; l++) {
        int i2 = tid + l * 256;
        int kc = i2 & 3, r = i2 >> 2;          // A: 128 rows x 4 k-chunks
        ar[l] = *(const float4*)(A + (size_t)(row0 + r) * K + kc * 4);
        int c4 = i2 & 31, rb = i2 >> 5;        // B: 16 rows x 32 col-chunks
        br[l] = *(const float4*)(B + (size_t)rb * N + col0 + c4 * 4);
    }
    // store tile 0
#pragma unroll
    for (int l = 0; l < 2; l++) {
        int i2 = tid + l * 256;
        int kc = i2 & 3, r = i2 >> 2;
        As[kc * 4 + 0][r] = ar[l].x;
        As[kc * 4 + 1][r] = ar[l].y;
        As[kc * 4 + 2][r] = ar[l].z;
        As[kc * 4 + 3][r] = ar[l].w;
        int c4 = i2 & 31, rb = i2 >> 5;
        *(float4*)&Bs[rb][c4 * 4] = br[l];
    }
    __syncthreads();

    for (int t = 1; t < ntiles; t++) {
        // prefetch next tile into regs
#pragma unroll
        for (int l = 0; l < 2; l++) {
            int i2 = tid + l * 256;
            int kc = i2 & 3, r = i2 >> 2;
            ar[l] = *(const float4*)(A + (size_t)(row0 + r) * K + t * GBK + kc * 4);
            int c4 = i2 & 31, rb = i2 >> 5;
            br[l] = *(const float4*)(B + (size_t)(t * GBK + rb) * N + col0 + c4 * 4);
        }
        // compute current tile
#pragma unroll
        for (int k = 0; k < GBK; k++) {
            float4 a0 = *(const float4*)&As[k][ty * 8];
            float4 a1 = *(const float4*)&As[k][ty * 8 + 4];
            float4 b0 = *(const float4*)&Bs[k][tx * 8];
            float4 b1 = *(const float4*)&Bs[k][tx * 8 + 4];
            float a[8] = {a0.x, a0.y, a0.z, a0.w, a1.x, a1.y, a1.z, a1.w};
            float b[8] = {b0.x, b0.y, b0.z, b0.w, b1.x, b1.y, b1.z, b1.w};
#pragma unroll
            for (int i = 0; i < 8; i++)
#pragma unroll
                for (int j = 0; j < 8; j++) acc[i][j] += a[i] * b[j];
        }
        __syncthreads();
        // store prefetched tile
#pragma unroll
        for (int l = 0; l < 2; l++) {
            int i2 = tid + l * 256;
            int kc = i2 & 3, r = i2 >> 2;
            As[kc * 4 + 0][r] = ar[l].x;
            As[kc * 4 + 1][r] = ar[l].y;
            As[kc * 4 + 2][r] = ar[l].z;
            As[kc * 4 + 3][r] = ar[l].w;
            int c4 = i2 & 31, rb = i2 >> 5;
            *(float4*)&Bs[rb][c4 * 4] = br[l];
        }
        __syncthreads();
    }
    // last tile compute
#pragma unroll
    for (int k = 0; k < GBK; k++) {
        float4 a0 = *(const float4*)&As[k][ty * 8];
        float4 a1 = *(const float4*)&As[k][ty * 8 + 4];
        float4 b0 = *(const float4*)&Bs[k][tx * 8];
        float4 b1 = *(const float4*)&Bs[k][tx * 8 + 4];
        float a[8] = {a0.x, a0.y, a0.z, a0.w, a1.x, a1.y, a1.z, a1.w};
        float b[8] = {b0.x, b0.y, b0.z, b0.w, b1.x, b1.y, b1.z, b1.w};
#pragma unroll
        for (int i = 0; i < 8; i++)
#pragma unroll
            for (int j = 0; j < 8; j++) acc[i][j] += a[i] * b[j];
    }

#pragma unroll
    for (int i = 0; i < 8; i++) {
        float* crow = C + (size_t)(row0 + ty * 8 + i) * N + col0 + tx * 8;
        *(float4*)crow = make_float4(acc[i][0], acc[i][1], acc[i][2], acc[i][3]);
        *(float4*)(crow + 4) = make_float4(acc[i][4], acc[i][5], acc[i][6], acc[i][7]);
    }
}

// ---------------------------------------------------------------------------
// Flash-style sparse attention. Block = (64-query tile, head). 256 threads.
// Chunks of 64 keys; scores + PV as register-tiled GEMMs; online softmax.
// ---------------------------------------------------------------------------
__global__ __launch_bounds__(256) void attn_kernel(const float* __restrict__ Q,
                                                   const float* __restrict__ Kg,
                                                   const float* __restrict__ Vg,
                                                   float* __restrict__ O) {
    __shared__ float Qs[64 * 64];   // [d][q], xor-swizzled float4 cols
    __shared__ float KPs[64 * 64];  // K: [d][kk] swizzled; later P: [q][kk] natural
    __shared__ float Vs[64 * 64];   // [kk][d] natural

    const int tid = threadIdx.x;
    const int tx = tid & 15;        // key / d-frag index
    const int ty = tid >> 4;        // query-frag index
    const int q0 = blockIdx.x * 64;
    const int h = blockIdx.y;
    const unsigned FULL = 0xffffffffu;

    // Load Q tile -> Qs[d][q] with xor swizzle on float4 column
#pragma unroll
    for (int l = 0; l < 4; l++) {
        int idx = tid + l * 256;
        int d4 = idx & 15, qq = idx >> 4;
        float4 v = *(const float4*)(Q + (size_t)(q0 + qq) * HID + h * HD + d4 * 4);
        float vv[4] = {v.x, v.y, v.z, v.w};
#pragma unroll
        for (int j = 0; j < 4; j++) {
            int d = d4 * 4 + j;
            Qs[d * 64 + (((qq >> 2) ^ (d & 15)) << 2) + (qq & 3)] = vv[j];
        }
    }

    float m[4], lsum[4], acc[4][4];
#pragma unroll
    for (int i = 0; i < 4; i++) {
        m[i] = -1e30f;
        lsum[i] = 0.f;
#pragma unroll
        for (int j = 0; j < 4; j++) acc[i][j] = 0.f;
    }

    const int c_start = max(0, q0 - 512);
    const int ng = (c_start + 511) >> 9;           // #globals strictly below c_start
    const int has_pro = (c_start > 0) ? 1 : 0;
    const int nwin = ((q0 - c_start) >> 6) + 1;
    const int nch = nwin + has_pro;

    for (int ci = 0; ci < nch; ci++) {
        const bool pro = has_pro && (ci == 0);
        const int base = pro ? 0 : c_start + (ci - has_pro) * 64;

        // --- load K (transposed+swizzled) and V (natural) chunk ---
#pragma unroll
        for (int l = 0; l < 4; l++) {
            int idx = tid + l * 256;
            int d4 = idx & 15, kk = idx >> 4;
            int j = pro ? ((kk < ng ? kk : 0) * 512) : (base + kk);
            float4 kv = *(const float4*)(Kg + (size_t)j * HID + h * HD + d4 * 4);
            float kvv[4] = {kv.x, kv.y, kv.z, kv.w};
#pragma unroll
            for (int jj = 0; jj < 4; jj++) {
                int d = d4 * 4 + jj;
                KPs[d * 64 + (((kk >> 2) ^ (d & 15)) << 2) + (kk & 3)] = kvv[jj];
            }
            float4 vv = *(const float4*)(Vg + (size_t)j * HID + h * HD + d4 * 4);
            *(float4*)&Vs[kk * 64 + d4 * 4] = vv;
        }
        __syncthreads();

        // --- scores: s[iq][ik] = Q[q] . K[kk] ---
        float s[4][4] = {};
#pragma unroll 16
        for (int d = 0; d < 64; d++) {
            float4 qf = *(const float4*)&Qs[d * 64 + ((ty ^ (d & 15)) << 2)];
            float4 kf = *(const float4*)&KPs[d * 64 + ((tx ^ (d & 15)) << 2)];
            float qa[4] = {qf.x, qf.y, qf.z, qf.w};
            float kb[4] = {kf.x, kf.y, kf.z, kf.w};
#pragma unroll
            for (int iq = 0; iq < 4; iq++)
#pragma unroll
                for (int ik = 0; ik < 4; ik++) s[iq][ik] += qa[iq] * kb[ik];
        }

        // --- mask + online softmax (row reduce over the 16 tx lanes) ---
#pragma unroll
        for (int iq = 0; iq < 4; iq++) {
            const int i = q0 + ty * 4 + iq;
            float rm = -1e30f;
#pragma unroll
            for (int ik = 0; ik < 4; ik++) {
                int kks = tx * 4 + ik;
                int j = pro ? kks * 512 : base + kks;
                bool valid = pro ? (kks < ng)
                                 : (j <= i && ((i - j) <= 512 || (j & 511) == 0));
                float sv = valid ? s[iq][ik] * 0.125f : -1e30f;
                s[iq][ik] = sv;
                rm = fmaxf(rm, sv);
            }
#pragma unroll
            for (int off = 1; off < 16; off <<= 1)
                rm = fmaxf(rm, __shfl_xor_sync(FULL, rm, off));
            float mn = fmaxf(m[iq], rm);
            float scf = __expf(m[iq] - mn);
            float rs = 0.f;
#pragma unroll
            for (int ik = 0; ik < 4; ik++) {
                float p = __expf(s[iq][ik] - mn);
                s[iq][ik] = p;
                rs += p;
            }
#pragma unroll
            for (int off = 1; off < 16; off <<= 1)
                rs += __shfl_xor_sync(FULL, rs, off);
            lsum[iq] = lsum[iq] * scf + rs;
#pragma unroll
            for (int id = 0; id < 4; id++) acc[iq][id] *= scf;
            m[iq] = mn;
        }
        __syncthreads();

        // --- store P[q][kk] (natural, STS.128) ---
#pragma unroll
        for (int iq = 0; iq < 4; iq++)
            *(float4*)&KPs[(ty * 4 + iq) * 64 + tx * 4] =
                make_float4(s[iq][0], s[iq][1], s[iq][2], s[iq][3]);
        __syncthreads();

        // --- PV: acc[iq][id] += P[q][kk] * V[kk][d] ---
#pragma unroll 4
        for (int kk4 = 0; kk4 < 16; kk4++) {
            float4 pf[4];
#pragma unroll
            for (int iq = 0; iq < 4; iq++)
                pf[iq] = *(const float4*)&KPs[(ty * 4 + iq) * 64 + kk4 * 4];
#pragma unroll
            for (int u = 0; u < 4; u++) {
                int kk = kk4 * 4 + u;
                float4 vf = *(const float4*)&Vs[kk * 64 + tx * 4];
                float vb[4] = {vf.x, vf.y, vf.z, vf.w};
                float pv[4] = {((const float*)&pf[0])[u], ((const float*)&pf[1])[u],
                               ((const float*)&pf[2])[u], ((const float*)&pf[3])[u]};
#pragma unroll
                for (int iq = 0; iq < 4; iq++)
#pragma unroll
                    for (int id = 0; id < 4; id++) acc[iq][id] += pv[iq] * vb[id];
            }
        }
        __syncthreads();
    }

    // epilogue
#pragma unroll
    for (int iq = 0; iq < 4; iq++) {
        float inv = 1.0f / lsum[iq];
        float* orow = O + (size_t)(q0 + ty * 4 + iq) * HID + h * HD + tx * 4;
        *(float4*)orow = make_float4(acc[iq][0] * inv, acc[iq][1] * inv,
                                     acc[iq][2] * inv, acc[iq][3] * inv);
    }
}

// ---------------------------------------------------------------------------
extern "C" void kernel_launch(void* const* d_in, const int* in_sizes, int n_in,
                              void* d_out, int out_size) {
    const float* x   = (const float*)d_in[0];
    const float* w_q = (const float*)d_in[1];
    const float* w_k = (const float*)d_in[2];
    const float* w_v = (const float*)d_in[3];
    const float* w_o = (const float*)d_in[4];
    float* out = (float*)d_out;

    float *q, *k, *v, *att;
    cudaGetSymbolAddress((void**)&q, g_q);
    cudaGetSymbolAddress((void**)&k, g_k);
    cudaGetSymbolAddress((void**)&v, g_v);
    cudaGetSymbolAddress((void**)&att, g_att);

    dim3 ggrid(HID / 128, S_LEN / 128);  // (8, 16)
    gemm_kernel<<<ggrid, 256>>>(x, w_q, q, S_LEN, HID, HID);
    gemm_kernel<<<ggrid, 256>>>(x, w_k, k, S_LEN, HID, HID);
    gemm_kernel<<<ggrid, 256>>>(x, w_v, v, S_LEN, HID, HID);

    dim3 agrid(S_LEN / 64, NH);          // (32, 16)
    attn_kernel<<<agrid, 256>>>(q, k, v, att);

    gemm_kernel<<<ggrid, 256>>>(att, w_o, out, S_LEN, HID, HID);
}

// round 3
// speedup vs baseline: 9.8356x; 1.5357x over previous
#include <cuda_runtime.h>
#include <cstdint>
#include <math.h>

#define S_LEN 2048
#define HID 1024
#define NH 16
#define HD 64

// Scratch (device globals; no allocation in kernel_launch)
__device__ float g_q[S_LEN * HID];
__device__ float g_k[S_LEN * HID];
__device__ float g_v[S_LEN * HID];
__device__ float g_att[S_LEN * HID];

__device__ __forceinline__ uint32_t f2tf(float x) {
    uint32_t u;
    asm("cvt.rna.tf32.f32 %0, %1;" : "=r"(u) : "f"(x));
    return u;
}

// swizzled index into a [16][128] tf32 tile: row k, logical col m.
// XOR mask 8*((k&3)^(k>>2)) makes transposed scalar stores AND mma-fragment
// scalar loads bank-conflict-free simultaneously.
__device__ __forceinline__ int swidx(int k, int m) {
    return (k << 7) + (m ^ ((((k & 3) ^ (k >> 2)) & 7) << 3));
}

// ---------------------------------------------------------------------------
// tf32 tensor-core GEMM: C[M,N] = A[M,K]*B[K,N]. 128x128 tile, BK=16,
// 256 threads, warp tile 64x32, mma.m16n8k8, double-buffered smem.
// ---------------------------------------------------------------------------
__global__ __launch_bounds__(256) void gemm_tf32(const float* __restrict__ A,
                                                 const float* __restrict__ B,
                                                 float* __restrict__ C,
                                                 int M, int N, int K) {
    __shared__ uint32_t As[2][16 * 128];
    __shared__ uint32_t Bs[2][16 * 128];

    const int tid = threadIdx.x;
    const int lane = tid & 31;
    const int w = tid >> 5;
    const int gid = lane >> 2;   // groupID 0..7
    const int tg = lane & 3;     // thread-in-group 0..3
    const int warp_m = (w & 1) * 64;
    const int warp_n = (w >> 1) * 32;
    const int row0 = blockIdx.y * 128;
    const int col0 = blockIdx.x * 128;

    float c[4][4][4];
#pragma unroll
    for (int i = 0; i < 4; i++)
#pragma unroll
        for (int j = 0; j < 4; j++)
#pragma unroll
            for (int r = 0; r < 4; r++) c[i][j][r] = 0.f;

    const int ntiles = K >> 4;
    float4 ar[2], br[2];

#define LOAD_G(t)                                                              \
    {                                                                          \
        _Pragma("unroll") for (int l = 0; l < 2; l++) {                        \
            int idx = tid + l * 256;                                           \
            int r = idx >> 2, c4 = idx & 3;                                    \
            ar[l] = *(const float4*)(A + (size_t)(row0 + r) * K + (t)*16 + c4 * 4); \
            int rb = idx >> 5, cb = idx & 31;                                  \
            br[l] = *(const float4*)(B + (size_t)((t)*16 + rb) * N + col0 + cb * 4); \
        }                                                                      \
    }

#define STORE_S(bf)                                                            \
    {                                                                          \
        _Pragma("unroll") for (int l = 0; l < 2; l++) {                        \
            int idx = tid + l * 256;                                           \
            int r = idx >> 2, c4 = idx & 3;                                    \
            As[bf][swidx(c4 * 4 + 0, r)] = f2tf(ar[l].x);                      \
            As[bf][swidx(c4 * 4 + 1, r)] = f2tf(ar[l].y);                      \
            As[bf][swidx(c4 * 4 + 2, r)] = f2tf(ar[l].z);                      \
            As[bf][swidx(c4 * 4 + 3, r)] = f2tf(ar[l].w);                      \
            int rb = idx >> 5, cb = idx & 31;                                  \
            int pc = (cb * 4) ^ ((((rb & 3) ^ (rb >> 2)) & 7) << 3);           \
            *(uint4*)&Bs[bf][(rb << 7) + pc] =                                 \
                make_uint4(f2tf(br[l].x), f2tf(br[l].y), f2tf(br[l].z), f2tf(br[l].w)); \
        }                                                                      \
    }

#define COMPUTE(bf)                                                            \
    {                                                                          \
        _Pragma("unroll") for (int ks = 0; ks < 2; ks++) {                     \
            int kb = ks * 8;                                                   \
            int k0 = kb + tg, k1 = kb + tg + 4;                                \
            uint32_t a[4][4], b[4][2];                                         \
            _Pragma("unroll") for (int mt = 0; mt < 4; mt++) {                 \
                int m = warp_m + mt * 16 + gid;                                \
                a[mt][0] = As[bf][swidx(k0, m)];                               \
                a[mt][1] = As[bf][swidx(k0, m + 8)];                           \
                a[mt][2] = As[bf][swidx(k1, m)];                               \
                a[mt][3] = As[bf][swidx(k1, m + 8)];                           \
            }                                                                  \
            _Pragma("unroll") for (int nt = 0; nt < 4; nt++) {                 \
                int n = warp_n + nt * 8 + gid;                                 \
                b[nt][0] = Bs[bf][swidx(k0, n)];                               \
                b[nt][1] = Bs[bf][swidx(k1, n)];                               \
            }                                                                  \
            _Pragma("unroll") for (int mt = 0; mt < 4; mt++)                   \
                _Pragma("unroll") for (int nt = 0; nt < 4; nt++) {             \
                    asm volatile(                                              \
                        "mma.sync.aligned.m16n8k8.row.col.f32.tf32.tf32.f32 " \
                        "{%0,%1,%2,%3}, {%4,%5,%6,%7}, {%8,%9}, {%0,%1,%2,%3};" \
                        : "+f"(c[mt][nt][0]), "+f"(c[mt][nt][1]),              \
                          "+f"(c[mt][nt][2]), "+f"(c[mt][nt][3])               \
                        : "r"(a[mt][0]), "r"(a[mt][1]), "r"(a[mt][2]),         \
                          "r"(a[mt][3]), "r"(b[nt][0]), "r"(b[nt][1]));        \
                }                                                              \
        }                                                                      \
    }

    LOAD_G(0);
    STORE_S(0);
    __syncthreads();

    for (int t = 0; t < ntiles; t++) {
        int buf = t & 1;
        if (t + 1 < ntiles) LOAD_G(t + 1);
        COMPUTE(buf);
        if (t + 1 < ntiles) {
            STORE_S(buf ^ 1);
            __syncthreads();
        }
    }

#pragma unroll
    for (int mt = 0; mt < 4; mt++)
#pragma unroll
        for (int nt = 0; nt < 4; nt++) {
            int row = row0 + warp_m + mt * 16 + gid;
            int col = col0 + warp_n + nt * 8 + tg * 2;
            float2 v01 = make_float2(c[mt][nt][0], c[mt][nt][1]);
            float2 v23 = make_float2(c[mt][nt][2], c[mt][nt][3]);
            *(float2*)&C[(size_t)row * N + col] = v01;
            *(float2*)&C[(size_t)(row + 8) * N + col] = v23;
        }
#undef LOAD_G
#undef STORE_S
#undef COMPUTE
}

// ---------------------------------------------------------------------------
// Flash-style sparse attention (fp32 SIMT, unchanged from R2).
// ---------------------------------------------------------------------------
__global__ __launch_bounds__(256) void attn_kernel(const float* __restrict__ Q,
                                                   const float* __restrict__ Kg,
                                                   const float* __restrict__ Vg,
                                                   float* __restrict__ O) {
    __shared__ float Qs[64 * 64];
    __shared__ float KPs[64 * 64];
    __shared__ float Vs[64 * 64];

    const int tid = threadIdx.x;
    const int tx = tid & 15;
    const int ty = tid >> 4;
    const int q0 = blockIdx.x * 64;
    const int h = blockIdx.y;
    const unsigned FULL = 0xffffffffu;

#pragma unroll
    for (int l = 0; l < 4; l++) {
        int idx = tid + l * 256;
        int d4 = idx & 15, qq = idx >> 4;
        float4 v = *(const float4*)(Q + (size_t)(q0 + qq) * HID + h * HD + d4 * 4);
        float vv[4] = {v.x, v.y, v.z, v.w};
#pragma unroll
        for (int j = 0; j < 4; j++) {
            int d = d4 * 4 + j;
            Qs[d * 64 + (((qq >> 2) ^ (d & 15)) << 2) + (qq & 3)] = vv[j];
        }
    }

    float m[4], lsum[4], acc[4][4];
#pragma unroll
    for (int i = 0; i < 4; i++) {
        m[i] = -1e30f;
        lsum[i] = 0.f;
#pragma unroll
        for (int j = 0; j < 4; j++) acc[i][j] = 0.f;
    }

    const int c_start = max(0, q0 - 512);
    const int ng = (c_start + 511) >> 9;
    const int has_pro = (c_start > 0) ? 1 : 0;
    const int nwin = ((q0 - c_start) >> 6) + 1;
    const int nch = nwin + has_pro;

    for (int ci = 0; ci < nch; ci++) {
        const bool pro = has_pro && (ci == 0);
        const int base = pro ? 0 : c_start + (ci - has_pro) * 64;

#pragma unroll
        for (int l = 0; l < 4; l++) {
            int idx = tid + l * 256;
            int d4 = idx & 15, kk = idx >> 4;
            int j = pro ? ((kk < ng ? kk : 0) * 512) : (base + kk);
            float4 kv = *(const float4*)(Kg + (size_t)j * HID + h * HD + d4 * 4);
            float kvv[4] = {kv.x, kv.y, kv.z, kv.w};
#pragma unroll
            for (int jj = 0; jj < 4; jj++) {
                int d = d4 * 4 + jj;
                KPs[d * 64 + (((kk >> 2) ^ (d & 15)) << 2) + (kk & 3)] = kvv[jj];
            }
            float4 vv = *(const float4*)(Vg + (size_t)j * HID + h * HD + d4 * 4);
            *(float4*)&Vs[kk * 64 + d4 * 4] = vv;
        }
        __syncthreads();

        float s[4][4] = {};
#pragma unroll 16
        for (int d = 0; d < 64; d++) {
            float4 qf = *(const float4*)&Qs[d * 64 + ((ty ^ (d & 15)) << 2)];
            float4 kf = *(const float4*)&KPs[d * 64 + ((tx ^ (d & 15)) << 2)];
            float qa[4] = {qf.x, qf.y, qf.z, qf.w};
            float kb[4] = {kf.x, kf.y, kf.z, kf.w};
#pragma unroll
            for (int iq = 0; iq < 4; iq++)
#pragma unroll
                for (int ik = 0; ik < 4; ik++) s[iq][ik] += qa[iq] * kb[ik];
        }

#pragma unroll
        for (int iq = 0; iq < 4; iq++) {
            const int i = q0 + ty * 4 + iq;
            float rm = -1e30f;
#pragma unroll
            for (int ik = 0; ik < 4; ik++) {
                int kks = tx * 4 + ik;
                int j = pro ? kks * 512 : base + kks;
                bool valid = pro ? (kks < ng)
                                 : (j <= i && ((i - j) <= 512 || (j & 511) == 0));
                float sv = valid ? s[iq][ik] * 0.125f : -1e30f;
                s[iq][ik] = sv;
                rm = fmaxf(rm, sv);
            }
#pragma unroll
            for (int off = 1; off < 16; off <<= 1)
                rm = fmaxf(rm, __shfl_xor_sync(FULL, rm, off));
            float mn = fmaxf(m[iq], rm);
            float scf = __expf(m[iq] - mn);
            float rs = 0.f;
#pragma unroll
            for (int ik = 0; ik < 4; ik++) {
                float p = __expf(s[iq][ik] - mn);
                s[iq][ik] = p;
                rs += p;
            }
#pragma unroll
            for (int off = 1; off < 16; off <<= 1)
                rs += __shfl_xor_sync(FULL, rs, off);
            lsum[iq] = lsum[iq] * scf + rs;
#pragma unroll
            for (int id = 0; id < 4; id++) acc[iq][id] *= scf;
            m[iq] = mn;
        }
        __syncthreads();

#pragma unroll
        for (int iq = 0; iq < 4; iq++)
            *(float4*)&KPs[(ty * 4 + iq) * 64 + tx * 4] =
                make_float4(s[iq][0], s[iq][1], s[iq][2], s[iq][3]);
        __syncthreads();

#pragma unroll 4
        for (int kk4 = 0; kk4 < 16; kk4++) {
            float4 pf[4];
#pragma unroll
            for (int iq = 0; iq < 4; iq++)
                pf[iq] = *(const float4*)&KPs[(ty * 4 + iq) * 64 + kk4 * 4];
#pragma unroll
            for (int u = 0; u < 4; u++) {
                int kk = kk4 * 4 + u;
                float4 vf = *(const float4*)&Vs[kk * 64 + tx * 4];
                float vb[4] = {vf.x, vf.y, vf.z, vf.w};
                float pv[4] = {((const float*)&pf[0])[u], ((const float*)&pf[1])[u],
                               ((const float*)&pf[2])[u], ((const float*)&pf[3])[u]};
#pragma unroll
                for (int iq = 0; iq < 4; iq++)
#pragma unroll
                    for (int id = 0; id < 4; id++) acc[iq][id] += pv[iq] * vb[id];
            }
        }
        __syncthreads();
    }

#pragma unroll
    for (int iq = 0; iq < 4; iq++) {
        float inv = 1.0f / lsum[iq];
        float* orow = O + (size_t)(q0 + ty * 4 + iq) * HID + h * HD + tx * 4;
        *(float4*)orow = make_float4(acc[iq][0] * inv, acc[iq][1] * inv,
                                     acc[iq][2] * inv, acc[iq][3] * inv);
    }
}

// ---------------------------------------------------------------------------
extern "C" void kernel_launch(void* const* d_in, const int* in_sizes, int n_in,
                              void* d_out, int out_size) {
    const float* x   = (const float*)d_in[0];
    const float* w_q = (const float*)d_in[1];
    const float* w_k = (const float*)d_in[2];
    const float* w_v = (const float*)d_in[3];
    const float* w_o = (const float*)d_in[4];
    float* out = (float*)d_out;

    float *q, *k, *v, *att;
    cudaGetSymbolAddress((void**)&q, g_q);
    cudaGetSymbolAddress((void**)&k, g_k);
    cudaGetSymbolAddress((void**)&v, g_v);
    cudaGetSymbolAddress((void**)&att, g_att);

    dim3 ggrid(HID / 128, S_LEN / 128);  // (8, 16)
    gemm_tf32<<<ggrid, 256>>>(x, w_q, q, S_LEN, HID, HID);
    gemm_tf32<<<ggrid, 256>>>(x, w_k, k, S_LEN, HID, HID);
    gemm_tf32<<<ggrid, 256>>>(x, w_v, v, S_LEN, HID, HID);

    dim3 agrid(S_LEN / 64, NH);          // (32, 16)
    attn_kernel<<<agrid, 256>>>(q, k, v, att);

    gemm_tf32<<<ggrid, 256>>>(att, w_o, out, S_LEN, HID, HID);
}

// round 7
// speedup vs baseline: 13.5364x; 1.3763x over previous
#include <cuda_runtime.h>
#include <cstdint>
#include <math.h>

#define S_LEN 2048
#define HID 1024
#define NH 16
#define HD 64

__device__ float g_q[S_LEN * HID];
__device__ float g_k[S_LEN * HID];
__device__ float g_v[S_LEN * HID];
__device__ float g_att[S_LEN * HID];

__device__ __forceinline__ uint32_t f2tf(float x) {
    uint32_t u;
    asm("cvt.rna.tf32.f32 %0, %1;" : "=r"(u) : "f"(x));
    return u;
}

__device__ __forceinline__ void mma_tf32(float* c, const uint32_t* a, uint32_t b0,
                                         uint32_t b1) {
    asm volatile(
        "mma.sync.aligned.m16n8k8.row.col.f32.tf32.tf32.f32 "
        "{%0,%1,%2,%3}, {%4,%5,%6,%7}, {%8,%9}, {%0,%1,%2,%3};"
        : "+f"(c[0]), "+f"(c[1]), "+f"(c[2]), "+f"(c[3])
        : "r"(a[0]), "r"(a[1]), "r"(a[2]), "r"(a[3]), "r"(b0), "r"(b1));
}

// swizzled index into a [16][128] tf32 tile (GEMM)
__device__ __forceinline__ int swidx(int k, int m) {
    return (k << 7) + (m ^ ((((k & 3) ^ (k >> 2)) & 7) << 3));
}

// ---------------------------------------------------------------------------
// tf32 GEMM body: 128x128 tile, BK=16, 256 threads, warp tile 64x32.
// ---------------------------------------------------------------------------
__device__ __forceinline__ void gemm_body(const float* __restrict__ A,
                                          const float* __restrict__ B,
                                          float* __restrict__ C, int row0, int col0,
                                          int N, int K) {
    __shared__ uint32_t As[2][16 * 128];
    __shared__ uint32_t Bs[2][16 * 128];

    const int tid = threadIdx.x;
    const int lane = tid & 31;
    const int w = tid >> 5;
    const int gid = lane >> 2;
    const int tg = lane & 3;
    const int warp_m = (w & 1) * 64;
    const int warp_n = (w >> 1) * 32;

    float c[4][4][4];
#pragma unroll
    for (int i = 0; i < 4; i++)
#pragma unroll
        for (int j = 0; j < 4; j++)
#pragma unroll
            for (int r = 0; r < 4; r++) c[i][j][r] = 0.f;

    const int ntiles = K >> 4;
    float4 ar[2], br[2];

#define LOAD_G(t)                                                                   \
    {                                                                               \
        _Pragma("unroll") for (int l = 0; l < 2; l++) {                             \
            int idx = tid + l * 256;                                                \
            int r = idx >> 2, c4 = idx & 3;                                         \
            ar[l] = *(const float4*)(A + (size_t)(row0 + r) * K + (t)*16 + c4 * 4); \
            int rb = idx >> 5, cb = idx & 31;                                       \
            br[l] = *(const float4*)(B + (size_t)((t)*16 + rb) * N + col0 + cb * 4);\
        }                                                                           \
    }

#define STORE_S(bf)                                                                 \
    {                                                                               \
        _Pragma("unroll") for (int l = 0; l < 2; l++) {                             \
            int idx = tid + l * 256;                                                \
            int r = idx >> 2, c4 = idx & 3;                                         \
            As[bf][swidx(c4 * 4 + 0, r)] = f2tf(ar[l].x);                           \
            As[bf][swidx(c4 * 4 + 1, r)] = f2tf(ar[l].y);                           \
            As[bf][swidx(c4 * 4 + 2, r)] = f2tf(ar[l].z);                           \
            As[bf][swidx(c4 * 4 + 3, r)] = f2tf(ar[l].w);                           \
            int rb = idx >> 5, cb = idx & 31;                                       \
            int pc = (cb * 4) ^ ((((rb & 3) ^ (rb >> 2)) & 7) << 3);                \
            *(uint4*)&Bs[bf][(rb << 7) + pc] = make_uint4(                          \
                f2tf(br[l].x), f2tf(br[l].y), f2tf(br[l].z), f2tf(br[l].w));        \
        }                                                                           \
    }

#define COMPUTE(bf)                                                                 \
    {                                                                               \
        _Pragma("unroll") for (int ks = 0; ks < 2; ks++) {                          \
            int kb = ks * 8;                                                        \
            int k0 = kb + tg, k1 = kb + tg + 4;                                     \
            uint32_t a[4][4], b[4][2];                                              \
            _Pragma("unroll") for (int mt = 0; mt < 4; mt++) {                      \
                int m = warp_m + mt * 16 + gid;                                     \
                a[mt][0] = As[bf][swidx(k0, m)];                                    \
                a[mt][1] = As[bf][swidx(k0, m + 8)];                                \
                a[mt][2] = As[bf][swidx(k1, m)];                                    \
                a[mt][3] = As[bf][swidx(k1, m + 8)];                                \
            }                                                                       \
            _Pragma("unroll") for (int nt = 0; nt < 4; nt++) {                      \
                int n = warp_n + nt * 8 + gid;                                      \
                b[nt][0] = Bs[bf][swidx(k0, n)];                                    \
                b[nt][1] = Bs[bf][swidx(k1, n)];                                    \
            }                                                                       \
            _Pragma("unroll") for (int mt = 0; mt < 4; mt++)                        \
                _Pragma("unroll") for (int nt = 0; nt < 4; nt++)                    \
                    mma_tf32(c[mt][nt], a[mt], b[nt][0], b[nt][1]);                 \
        }                                                                           \
    }

    LOAD_G(0);
    STORE_S(0);
    __syncthreads();

    for (int t = 0; t < ntiles; t++) {
        int buf = t & 1;
        if (t + 1 < ntiles) LOAD_G(t + 1);
        COMPUTE(buf);
        if (t + 1 < ntiles) {
            STORE_S(buf ^ 1);
            __syncthreads();
        }
    }

#pragma unroll
    for (int mt = 0; mt < 4; mt++)
#pragma unroll
        for (int nt = 0; nt < 4; nt++) {
            int row = row0 + warp_m + mt * 16 + gid;
            int col = col0 + warp_n + nt * 8 + tg * 2;
            *(float2*)&C[(size_t)row * N + col] = make_float2(c[mt][nt][0], c[mt][nt][1]);
            *(float2*)&C[(size_t)(row + 8) * N + col] =
                make_float2(c[mt][nt][2], c[mt][nt][3]);
        }
#undef LOAD_G
#undef STORE_S
#undef COMPUTE
}

__global__ __launch_bounds__(256) void gemm_tf32(const float* __restrict__ A,
                                                 const float* __restrict__ B,
                                                 float* __restrict__ C, int N, int K) {
    gemm_body(A, B, C, blockIdx.y * 128, blockIdx.x * 128, N, K);
}

__global__ __launch_bounds__(256) void gemm_qkv(const float* __restrict__ A,
                                                const float* __restrict__ B0,
                                                const float* __restrict__ B1,
                                                const float* __restrict__ B2,
                                                float* __restrict__ C0,
                                                float* __restrict__ C1,
                                                float* __restrict__ C2, int N, int K) {
    int sel = blockIdx.x >> 3;
    const float* B = (sel == 0) ? B0 : (sel == 1) ? B1 : B2;
    float* C = (sel == 0) ? C0 : (sel == 1) ? C1 : C2;
    gemm_body(A, B, C, blockIdx.y * 128, (blockIdx.x & 7) * 128, N, K);
}

// ---------------------------------------------------------------------------
// Tensor-core flash sparse attention. Block = (64-query tile, head), 128 thr.
// STATIC shared memory: K tile and P tile alias the same buffer (K is dead
// after the score MMAs; a __syncthreads separates the phases).
// ---------------------------------------------------------------------------
#define KS_STRIDE 65
#define VS_STRIDE 68
#define PS_STRIDE 72

__global__ __launch_bounds__(128) void attn_mma(const float* __restrict__ Q,
                                                const float* __restrict__ Kg,
                                                const float* __restrict__ Vg,
                                                float* __restrict__ O) {
    __shared__ uint32_t KPs[64 * PS_STRIDE];  // K view stride 65 / P view stride 72
    __shared__ uint32_t Vs[64 * VS_STRIDE];   // [j][d] natural, xor swizzle

    const int tid = threadIdx.x;
    const int lane = tid & 31;
    const int w = tid >> 5;
    const int gid = lane >> 2;
    const int tg = lane & 3;
    const int wm = w * 16;
    const int q0 = blockIdx.x * 64;
    const int hb = blockIdx.y * HD;
    const unsigned FULL = 0xffffffffu;

    // Q fragments (persist all chunks)
    uint32_t qa[8][4];
    {
        const float* qp = Q + (size_t)(q0 + wm + gid) * HID + hb;
#pragma unroll
        for (int ks = 0; ks < 8; ks++) {
            qa[ks][0] = f2tf(qp[ks * 8 + tg]);
            qa[ks][1] = f2tf(qp[8 * HID + ks * 8 + tg]);
            qa[ks][2] = f2tf(qp[ks * 8 + tg + 4]);
            qa[ks][3] = f2tf(qp[8 * HID + ks * 8 + tg + 4]);
        }
    }

    float m[2] = {-1e30f, -1e30f}, lsum[2] = {0.f, 0.f};
    float o[8][4];
#pragma unroll
    for (int nt = 0; nt < 8; nt++)
#pragma unroll
        for (int r = 0; r < 4; r++) o[nt][r] = 0.f;

    const int c_start = max(0, q0 - 512);
    const int ng = (c_start + 511) >> 9;
    const int has_pro = (c_start > 0) ? 1 : 0;
    const int nch = ((q0 - c_start) >> 6) + 1 + has_pro;

    for (int ci = 0; ci < nch; ci++) {
        const bool pro = has_pro && (ci == 0);
        const int base = pro ? 0 : c_start + (ci - has_pro) * 64;

        // --- cooperative K (transposed, stride 65) / V (natural) load ---
#pragma unroll
        for (int l2 = 0; l2 < 8; l2++) {
            int idx = tid + l2 * 128;
            int d4 = idx & 15, kk = idx >> 4;
            int j = pro ? ((kk < ng ? kk : 0) << 9) : (base + kk);
            float4 kv = *(const float4*)(Kg + (size_t)j * HID + hb + d4 * 4);
            const float* kvp = (const float*)&kv;
#pragma unroll
            for (int u = 0; u < 4; u++)
                KPs[(d4 * 4 + u) * KS_STRIDE + (kk ^ (u << 3))] = f2tf(kvp[u]);
            float4 vv = *(const float4*)(Vg + (size_t)j * HID + hb + d4 * 4);
            *(uint4*)&Vs[kk * VS_STRIDE + ((d4 * 4) ^ ((kk & 3) << 3))] =
                make_uint4(f2tf(vv.x), f2tf(vv.y), f2tf(vv.z), f2tf(vv.w));
        }
        __syncthreads();

        // --- scores: S[16q x 64j] per warp ---
        float s[8][4];
#pragma unroll
        for (int nt = 0; nt < 8; nt++)
#pragma unroll
            for (int r = 0; r < 4; r++) s[nt][r] = 0.f;

#pragma unroll
        for (int ks = 0; ks < 8; ks++) {
            int d0 = tg + 8 * ks, d1 = tg + 4 + 8 * ks;
#pragma unroll
            for (int nt = 0; nt < 8; nt++) {
                int cx = (gid + 8 * nt) ^ (tg << 3);
                uint32_t b0 = KPs[d0 * KS_STRIDE + cx];
                uint32_t b1 = KPs[d1 * KS_STRIDE + cx];
                mma_tf32(s[nt], qa[ks], b0, b1);
            }
        }
        __syncthreads();  // all warps done reading K before P overwrites buffer

        // --- mask + online softmax + P store (stride 72, warp-private rows) ---
#pragma unroll
        for (int r = 0; r < 2; r++) {
            const int i = q0 + wm + gid + 8 * r;
            float rm = -1e30f;
#pragma unroll
            for (int nt = 0; nt < 8; nt++) {
#pragma unroll
                for (int dj = 0; dj < 2; dj++) {
                    int jj = 8 * nt + 2 * tg + dj;
                    bool valid;
                    if (pro) {
                        valid = jj < ng;
                    } else {
                        int j = base + jj;
                        valid = (j <= i) && ((i - j) <= 512 || (j & 511) == 0);
                    }
                    float x = valid ? s[nt][2 * r + dj] * 0.125f : -1e30f;
                    s[nt][2 * r + dj] = x;
                    rm = fmaxf(rm, x);
                }
            }
            rm = fmaxf(rm, __shfl_xor_sync(FULL, rm, 1));
            rm = fmaxf(rm, __shfl_xor_sync(FULL, rm, 2));
            float mn = fmaxf(m[r], rm);
            float scf = __expf(m[r] - mn);
            m[r] = mn;
            float rs = 0.f;
            uint32_t* prow = KPs + (wm + gid + 8 * r) * PS_STRIDE;
#pragma unroll
            for (int nt = 0; nt < 8; nt++) {
                float p0 = __expf(s[nt][2 * r] - mn);
                float p1 = __expf(s[nt][2 * r + 1] - mn);
                rs += p0 + p1;
                *(uint2*)&prow[8 * nt + 2 * tg] = make_uint2(f2tf(p0), f2tf(p1));
                o[nt][2 * r] *= scf;
                o[nt][2 * r + 1] *= scf;
            }
            rs += __shfl_xor_sync(FULL, rs, 1);
            rs += __shfl_xor_sync(FULL, rs, 2);
            lsum[r] = lsum[r] * scf + rs;
        }
        __syncwarp();

        // --- PV: O[16q x 64d] += P * V (reads only this warp's P rows) ---
        const uint32_t* prow0 = KPs + (wm + gid) * PS_STRIDE;
#pragma unroll
        for (int ks = 0; ks < 8; ks++) {
            uint32_t pa[4];
            pa[0] = prow0[8 * ks + tg];
            pa[1] = prow0[8 * PS_STRIDE + 8 * ks + tg];
            pa[2] = prow0[8 * ks + tg + 4];
            pa[3] = prow0[8 * PS_STRIDE + 8 * ks + tg + 4];
            int j0 = tg + 8 * ks, j1 = tg + 4 + 8 * ks;
#pragma unroll
            for (int nt = 0; nt < 8; nt++) {
                int cx = (gid + 8 * nt) ^ (tg << 3);
                uint32_t vb0 = Vs[j0 * VS_STRIDE + cx];
                uint32_t vb1 = Vs[j1 * VS_STRIDE + cx];
                mma_tf32(o[nt], pa, vb0, vb1);
            }
        }
        __syncthreads();  // P buffer + V dead before next chunk's loads
    }

    // --- epilogue ---
#pragma unroll
    for (int r = 0; r < 2; r++) {
        float inv = 1.0f / lsum[r];
        float* orow = O + (size_t)(q0 + wm + gid + 8 * r) * HID + hb;
#pragma unroll
        for (int nt = 0; nt < 8; nt++)
            *(float2*)&orow[8 * nt + 2 * tg] =
                make_float2(o[nt][2 * r] * inv, o[nt][2 * r + 1] * inv);
    }
}

// ---------------------------------------------------------------------------
extern "C" void kernel_launch(void* const* d_in, const int* in_sizes, int n_in,
                              void* d_out, int out_size) {
    const float* x   = (const float*)d_in[0];
    const float* w_q = (const float*)d_in[1];
    const float* w_k = (const float*)d_in[2];
    const float* w_v = (const float*)d_in[3];
    const float* w_o = (const float*)d_in[4];
    float* out = (float*)d_out;

    float *q, *k, *v, *att;
    cudaGetSymbolAddress((void**)&q, g_q);
    cudaGetSymbolAddress((void**)&k, g_k);
    cudaGetSymbolAddress((void**)&v, g_v);
    cudaGetSymbolAddress((void**)&att, g_att);

    gemm_qkv<<<dim3(24, 16), 256>>>(x, w_q, w_k, w_v, q, k, v, HID, HID);

    attn_mma<<<dim3(S_LEN / 64, NH), 128>>>(q, k, v, att);

    gemm_tf32<<<dim3(8, 16), 256>>>(att, w_o, out, HID, HID);
}

// round 11
// speedup vs baseline: 15.6756x; 1.1580x over previous
#include <cuda_runtime.h>
#include <cstdint>
#include <math.h>

#define S_LEN 2048
#define HID 1024
#define NH 16
#define HD 64

__device__ float g_q[S_LEN * HID];
__device__ float g_k[S_LEN * HID];
__device__ float g_v[S_LEN * HID];
__device__ float g_att[S_LEN * HID];

__device__ __forceinline__ uint32_t f2tf(float x) {
    uint32_t u;
    asm("cvt.rna.tf32.f32 %0, %1;" : "=r"(u) : "f"(x));
    return u;
}

__device__ __forceinline__ void mma_tf32(float* c, const uint32_t* a, uint32_t b0,
                                         uint32_t b1) {
    asm volatile(
        "mma.sync.aligned.m16n8k8.row.col.f32.tf32.tf32.f32 "
        "{%0,%1,%2,%3}, {%4,%5,%6,%7}, {%8,%9}, {%0,%1,%2,%3};"
        : "+f"(c[0]), "+f"(c[1]), "+f"(c[2]), "+f"(c[3])
        : "r"(a[0]), "r"(a[1]), "r"(a[2]), "r"(a[3]), "r"(b0), "r"(b1));
}

// swizzled index into a [16][128] tf32 tile (GEMM)
__device__ __forceinline__ int swidx(int k, int m) {
    return (k << 7) + (m ^ ((((k & 3) ^ (k >> 2)) & 7) << 3));
}

// ---------------------------------------------------------------------------
// tf32 GEMM body, N=K=1024 compile-time. 128x128 tile, BK=16, 256 threads,
// warp tile 64x32. Software-pipelined x2: constant buffer indices, zero
// conditionals in the steady state -> all smem addresses loop-invariant.
// ---------------------------------------------------------------------------
#define GN 1024
#define GK 1024

__device__ __forceinline__ void gemm_body(const float* __restrict__ A,
                                          const float* __restrict__ B,
                                          float* __restrict__ C, int row0, int col0) {
    __shared__ uint32_t As[2][16 * 128];
    __shared__ uint32_t Bs[2][16 * 128];

    const int tid = threadIdx.x;
    const int lane = tid & 31;
    const int w = tid >> 5;
    const int gid = lane >> 2;
    const int tg = lane & 3;
    const int warp_m = (w & 1) * 64;
    const int warp_n = (w >> 1) * 32;

    // global pointers (t-invariant bases, incremented per tile-pair)
    const int r0 = tid >> 2, c0 = (tid & 3) * 4;
    const int rb0 = tid >> 5, cbc = (tid & 31) * 4;
    const float* pa = A + (size_t)(row0 + r0) * GK + c0;
    const float* pb = B + (size_t)rb0 * GN + col0 + cbc;

    // t-invariant smem store offsets
    int sa[4];
#pragma unroll
    for (int u = 0; u < 4; u++) sa[u] = swidx(c0 + u, r0);  // row r0+64 = +64
    const int sb0 = (rb0 << 7) + (cbc ^ ((((rb0 & 3) ^ (rb0 >> 2)) & 7) << 3));
    const int rb1 = rb0 + 8;
    const int sb1 = (rb1 << 7) + (cbc ^ ((((rb1 & 3) ^ (rb1 >> 2)) & 7) << 3));

    float c[4][4][4];
#pragma unroll
    for (int i = 0; i < 4; i++)
#pragma unroll
        for (int j = 0; j < 4; j++)
#pragma unroll
            for (int r = 0; r < 4; r++) c[i][j][r] = 0.f;

    float4 ar0, ar1, br0, br1;

#define LOAD_G()                                         \
    {                                                    \
        ar0 = *(const float4*)pa;                        \
        ar1 = *(const float4*)(pa + (size_t)64 * GK);    \
        br0 = *(const float4*)pb;                        \
        br1 = *(const float4*)(pb + (size_t)8 * GN);     \
        pa += 16;                                        \
        pb += (size_t)16 * GN;                           \
    }

#define STORE_S(bf)                                                            \
    {                                                                          \
        const float* a0 = (const float*)&ar0;                                  \
        const float* a1 = (const float*)&ar1;                                  \
        _Pragma("unroll") for (int u = 0; u < 4; u++) {                        \
            As[bf][sa[u]] = f2tf(a0[u]);                                       \
            As[bf][sa[u] + 64] = f2tf(a1[u]);                                  \
        }                                                                      \
        *(uint4*)&Bs[bf][sb0] =                                                \
            make_uint4(f2tf(br0.x), f2tf(br0.y), f2tf(br0.z), f2tf(br0.w));    \
        *(uint4*)&Bs[bf][sb1] =                                                \
            make_uint4(f2tf(br1.x), f2tf(br1.y), f2tf(br1.z), f2tf(br1.w));    \
    }

#define COMPUTE(bf)                                                            \
    {                                                                          \
        _Pragma("unroll") for (int ks = 0; ks < 2; ks++) {                     \
            int kb = ks * 8;                                                   \
            int k0 = kb + tg, k1 = kb + tg + 4;                                \
            uint32_t a[4][4], b[4][2];                                         \
            _Pragma("unroll") for (int mt = 0; mt < 4; mt++) {                 \
                int m = warp_m + mt * 16 + gid;                                \
                a[mt][0] = As[bf][swidx(k0, m)];                               \
                a[mt][1] = As[bf][swidx(k0, m + 8)];                           \
                a[mt][2] = As[bf][swidx(k1, m)];                               \
                a[mt][3] = As[bf][swidx(k1, m + 8)];                           \
            }                                                                  \
            _Pragma("unroll") for (int nt = 0; nt < 4; nt++) {                 \
                int n = warp_n + nt * 8 + gid;                                 \
                b[nt][0] = Bs[bf][swidx(k0, n)];                               \
                b[nt][1] = Bs[bf][swidx(k1, n)];                               \
            }                                                                  \
            _Pragma("unroll") for (int mt = 0; mt < 4; mt++)                   \
                _Pragma("unroll") for (int nt = 0; nt < 4; nt++)               \
                    mma_tf32(c[mt][nt], a[mt], b[nt][0], b[nt][1]);            \
        }                                                                      \
    }

    // prologue: tile0 -> buf0; tile1 -> regs
    LOAD_G();
    STORE_S(0);
    __syncthreads();
    LOAD_G();

    // steady state: tiles t(buf0), t+1(buf1); 62 tiles over 31 iterations
#pragma unroll 1
    for (int t = 0; t < 62; t += 2) {
        COMPUTE(0);
        STORE_S(1);
        __syncthreads();
        LOAD_G();
        COMPUTE(1);
        STORE_S(0);
        __syncthreads();
        LOAD_G();
    }
    // epilogue: regs hold tile 63, buf0 holds tile 62
    COMPUTE(0);
    STORE_S(1);
    __syncthreads();
    COMPUTE(1);

#pragma unroll
    for (int mt = 0; mt < 4; mt++)
#pragma unroll
        for (int nt = 0; nt < 4; nt++) {
            int row = row0 + warp_m + mt * 16 + gid;
            int col = col0 + warp_n + nt * 8 + tg * 2;
            *(float2*)&C[(size_t)row * GN + col] =
                make_float2(c[mt][nt][0], c[mt][nt][1]);
            *(float2*)&C[(size_t)(row + 8) * GN + col] =
                make_float2(c[mt][nt][2], c[mt][nt][3]);
        }
#undef LOAD_G
#undef STORE_S
#undef COMPUTE
}

__global__ __launch_bounds__(256) void gemm_tf32(const float* __restrict__ A,
                                                 const float* __restrict__ B,
                                                 float* __restrict__ C) {
    gemm_body(A, B, C, blockIdx.y * 128, blockIdx.x * 128);
}

__global__ __launch_bounds__(256) void gemm_qkv(const float* __restrict__ A,
                                                const float* __restrict__ B0,
                                                const float* __restrict__ B1,
                                                const float* __restrict__ B2,
                                                float* __restrict__ C0,
                                                float* __restrict__ C1,
                                                float* __restrict__ C2) {
    int sel = blockIdx.x >> 3;
    const float* B = (sel == 0) ? B0 : (sel == 1) ? B1 : B2;
    float* C = (sel == 0) ? C0 : (sel == 1) ? C1 : C2;
    gemm_body(A, B, C, blockIdx.y * 128, (blockIdx.x & 7) * 128);
}

// ---------------------------------------------------------------------------
// Tensor-core flash sparse attention (unchanged from R7 passing version).
// ---------------------------------------------------------------------------
#define KS_STRIDE 65
#define VS_STRIDE 68
#define PS_STRIDE 72

__global__ __launch_bounds__(128) void attn_mma(const float* __restrict__ Q,
                                                const float* __restrict__ Kg,
                                                const float* __restrict__ Vg,
                                                float* __restrict__ O) {
    __shared__ uint32_t KPs[64 * PS_STRIDE];  // K view stride 65 / P view stride 72
    __shared__ uint32_t Vs[64 * VS_STRIDE];   // [j][d] natural, xor swizzle

    const int tid = threadIdx.x;
    const int lane = tid & 31;
    const int w = tid >> 5;
    const int gid = lane >> 2;
    const int tg = lane & 3;
    const int wm = w * 16;
    const int q0 = blockIdx.x * 64;
    const int hb = blockIdx.y * HD;
    const unsigned FULL = 0xffffffffu;

    uint32_t qa[8][4];
    {
        const float* qp = Q + (size_t)(q0 + wm + gid) * HID + hb;
#pragma unroll
        for (int ks = 0; ks < 8; ks++) {
            qa[ks][0] = f2tf(qp[ks * 8 + tg]);
            qa[ks][1] = f2tf(qp[8 * HID + ks * 8 + tg]);
            qa[ks][2] = f2tf(qp[ks * 8 + tg + 4]);
            qa[ks][3] = f2tf(qp[8 * HID + ks * 8 + tg + 4]);
        }
    }

    float m[2] = {-1e30f, -1e30f}, lsum[2] = {0.f, 0.f};
    float o[8][4];
#pragma unroll
    for (int nt = 0; nt < 8; nt++)
#pragma unroll
        for (int r = 0; r < 4; r++) o[nt][r] = 0.f;

    const int c_start = max(0, q0 - 512);
    const int ng = (c_start + 511) >> 9;
    const int has_pro = (c_start > 0) ? 1 : 0;
    const int nch = ((q0 - c_start) >> 6) + 1 + has_pro;

    for (int ci = 0; ci < nch; ci++) {
        const bool pro = has_pro && (ci == 0);
        const int base = pro ? 0 : c_start + (ci - has_pro) * 64;

#pragma unroll
        for (int l2 = 0; l2 < 8; l2++) {
            int idx = tid + l2 * 128;
            int d4 = idx & 15, kk = idx >> 4;
            int j = pro ? ((kk < ng ? kk : 0) << 9) : (base + kk);
            float4 kv = *(const float4*)(Kg + (size_t)j * HID + hb + d4 * 4);
            const float* kvp = (const float*)&kv;
#pragma unroll
            for (int u = 0; u < 4; u++)
                KPs[(d4 * 4 + u) * KS_STRIDE + (kk ^ (u << 3))] = f2tf(kvp[u]);
            float4 vv = *(const float4*)(Vg + (size_t)j * HID + hb + d4 * 4);
            *(uint4*)&Vs[kk * VS_STRIDE + ((d4 * 4) ^ ((kk & 3) << 3))] =
                make_uint4(f2tf(vv.x), f2tf(vv.y), f2tf(vv.z), f2tf(vv.w));
        }
        __syncthreads();

        float s[8][4];
#pragma unroll
        for (int nt = 0; nt < 8; nt++)
#pragma unroll
            for (int r = 0; r < 4; r++) s[nt][r] = 0.f;

#pragma unroll
        for (int ks = 0; ks < 8; ks++) {
            int d0 = tg + 8 * ks, d1 = tg + 4 + 8 * ks;
#pragma unroll
            for (int nt = 0; nt < 8; nt++) {
                int cx = (gid + 8 * nt) ^ (tg << 3);
                uint32_t b0 = KPs[d0 * KS_STRIDE + cx];
                uint32_t b1 = KPs[d1 * KS_STRIDE + cx];
                mma_tf32(s[nt], qa[ks], b0, b1);
            }
        }
        __syncthreads();

#pragma unroll
        for (int r = 0; r < 2; r++) {
            const int i = q0 + wm + gid + 8 * r;
            float rm = -1e30f;
#pragma unroll
            for (int nt = 0; nt < 8; nt++) {
#pragma unroll
                for (int dj = 0; dj < 2; dj++) {
                    int jj = 8 * nt + 2 * tg + dj;
                    bool valid;
                    if (pro) {
                        valid = jj < ng;
                    } else {
                        int j = base + jj;
                        valid = (j <= i) && ((i - j) <= 512 || (j & 511) == 0);
                    }
                    float x = valid ? s[nt][2 * r + dj] * 0.125f : -1e30f;
                    s[nt][2 * r + dj] = x;
                    rm = fmaxf(rm, x);
                }
            }
            rm = fmaxf(rm, __shfl_xor_sync(FULL, rm, 1));
            rm = fmaxf(rm, __shfl_xor_sync(FULL, rm, 2));
            float mn = fmaxf(m[r], rm);
            float scf = __expf(m[r] - mn);
            m[r] = mn;
            float rs = 0.f;
            uint32_t* prow = KPs + (wm + gid + 8 * r) * PS_STRIDE;
#pragma unroll
            for (int nt = 0; nt < 8; nt++) {
                float p0 = __expf(s[nt][2 * r] - mn);
                float p1 = __expf(s[nt][2 * r + 1] - mn);
                rs += p0 + p1;
                *(uint2*)&prow[8 * nt + 2 * tg] = make_uint2(f2tf(p0), f2tf(p1));
                o[nt][2 * r] *= scf;
                o[nt][2 * r + 1] *= scf;
            }
            rs += __shfl_xor_sync(FULL, rs, 1);
            rs += __shfl_xor_sync(FULL, rs, 2);
            lsum[r] = lsum[r] * scf + rs;
        }
        __syncwarp();

        const uint32_t* prow0 = KPs + (wm + gid) * PS_STRIDE;
#pragma unroll
        for (int ks = 0; ks < 8; ks++) {
            uint32_t pa[4];
            pa[0] = prow0[8 * ks + tg];
            pa[1] = prow0[8 * PS_STRIDE + 8 * ks + tg];
            pa[2] = prow0[8 * ks + tg + 4];
            pa[3] = prow0[8 * PS_STRIDE + 8 * ks + tg + 4];
            int j0 = tg + 8 * ks, j1 = tg + 4 + 8 * ks;
#pragma unroll
            for (int nt = 0; nt < 8; nt++) {
                int cx = (gid + 8 * nt) ^ (tg << 3);
                uint32_t vb0 = Vs[j0 * VS_STRIDE + cx];
                uint32_t vb1 = Vs[j1 * VS_STRIDE + cx];
                mma_tf32(o[nt], pa, vb0, vb1);
            }
        }
        __syncthreads();
    }

#pragma unroll
    for (int r = 0; r < 2; r++) {
        float inv = 1.0f / lsum[r];
        float* orow = O + (size_t)(q0 + wm + gid + 8 * r) * HID + hb;
#pragma unroll
        for (int nt = 0; nt < 8; nt++)
            *(float2*)&orow[8 * nt + 2 * tg] =
                make_float2(o[nt][2 * r] * inv, o[nt][2 * r + 1] * inv);
    }
}

// ---------------------------------------------------------------------------
extern "C" void kernel_launch(void* const* d_in, const int* in_sizes, int n_in,
                              void* d_out, int out_size) {
    const float* x   = (const float*)d_in[0];
    const float* w_q = (const float*)d_in[1];
    const float* w_k = (const float*)d_in[2];
    const float* w_v = (const float*)d_in[3];
    const float* w_o = (const float*)d_in[4];
    float* out = (float*)d_out;

    float *q, *k, *v, *att;
    cudaGetSymbolAddress((void**)&q, g_q);
    cudaGetSymbolAddress((void**)&k, g_k);
    cudaGetSymbolAddress((void**)&v, g_v);
    cudaGetSymbolAddress((void**)&att, g_att);

    gemm_qkv<<<dim3(24, 16), 256>>>(x, w_q, w_k, w_v, q, k, v);

    attn_mma<<<dim3(S_LEN / 64, NH), 128>>>(q, k, v, att);

    gemm_tf32<<<dim3(8, 16), 256>>>(att, w_o, out);
}

// round 12
// speedup vs baseline: 18.0143x; 1.1492x over previous
#include <cuda_runtime.h>
#include <cstdint>
#include <math.h>

#define S_LEN 2048
#define HID 1024
#define NH 16
#define HD 64
#define GN 1024
#define GK 1024

__device__ float g_q[S_LEN * HID];
__device__ float g_k[S_LEN * HID];
__device__ float g_v[S_LEN * HID];
__device__ float g_att[S_LEN * HID];
// tf32-rounded copies of the inputs
__device__ float g_xc[S_LEN * HID];
__device__ float g_wq[HID * HID];
__device__ float g_wk[HID * HID];
__device__ float g_wv[HID * HID];
__device__ float g_wo[HID * HID];

__device__ __forceinline__ uint32_t f2tf(float x) {
    uint32_t u;
    asm("cvt.rna.tf32.f32 %0, %1;" : "=r"(u) : "f"(x));
    return u;
}

__device__ __forceinline__ void mma_tf32(float* c, const uint32_t* a, uint32_t b0,
                                         uint32_t b1) {
    asm volatile(
        "mma.sync.aligned.m16n8k8.row.col.f32.tf32.tf32.f32 "
        "{%0,%1,%2,%3}, {%4,%5,%6,%7}, {%8,%9}, {%0,%1,%2,%3};"
        : "+f"(c[0]), "+f"(c[1]), "+f"(c[2]), "+f"(c[3])
        : "r"(a[0]), "r"(a[1]), "r"(a[2]), "r"(a[3]), "r"(b0), "r"(b1));
}

__device__ __forceinline__ void cp16(uint32_t dst, const float* src) {
    asm volatile("cp.async.cg.shared.global [%0], [%1], 16;" ::"r"(dst), "l"(src));
}
__device__ __forceinline__ void cp_commit() {
    asm volatile("cp.async.commit_group;");
}
template <int N>
__device__ __forceinline__ void cp_wait() {
    asm volatile("cp.async.wait_group %0;" ::"n"(N));
}

// ---------------------------------------------------------------------------
// Pre-convert inputs to tf32 (rna), stored as fp32 bit patterns.
// ---------------------------------------------------------------------------
__global__ __launch_bounds__(256) void cvt_inputs(
    const float* __restrict__ x, const float* __restrict__ wq,
    const float* __restrict__ wk, const float* __restrict__ wv,
    const float* __restrict__ wo, float* __restrict__ xc, float* __restrict__ wqc,
    float* __restrict__ wkc, float* __restrict__ wvc, float* __restrict__ woc) {
    int i = blockIdx.x * 256 + threadIdx.x;  // over float4s: 1.5M total
    const float* src;
    float* dst;
    int off;
    if (i < 524288) {
        src = x; dst = xc; off = i;
    } else {
        int r = i - 524288;
        int w = r >> 18;          // 0..3
        off = r & 262143;
        src = (w == 0) ? wq : (w == 1) ? wk : (w == 2) ? wv : wo;
        dst = (w == 0) ? wqc : (w == 1) ? wkc : (w == 2) ? wvc : woc;
    }
    float4 v = *(const float4*)(src + (size_t)off * 4);
    uint4 o = make_uint4(f2tf(v.x), f2tf(v.y), f2tf(v.z), f2tf(v.w));
    *(uint4*)(dst + (size_t)off * 4) = o;
}

// ---------------------------------------------------------------------------
// cp.async tf32 GEMM: 128x128 tile, BK=16, 3-stage pipeline, 256 threads,
// warp tile 64x32. Inputs must already be tf32-rounded. ROUND_C: round output.
// Smem: A [m][16w] chunk-swizzled ^((m>>1)&3); B [k][128w] swizzled ^(2*(k&3)).
// ---------------------------------------------------------------------------
template <bool ROUND_C>
__device__ __forceinline__ void gemm_body(const float* __restrict__ A,
                                          const float* __restrict__ B,
                                          float* __restrict__ C, int row0, int col0) {
    __shared__ uint32_t As[3][2048];
    __shared__ uint32_t Bs[3][2048];

    const int tid = threadIdx.x;
    const int lane = tid & 31;
    const int w = tid >> 5;
    const int gid = lane >> 2;
    const int tg = lane & 3;
    const int warp_m = (w & 1) * 64;
    const int warp_n = (w >> 1) * 32;

    // cp.async src pointers / dst offsets (t-invariant)
    const int ra = tid >> 1, ca = (tid & 1) * 2;
    const int rb = tid >> 4, cb = (tid & 15) * 2;
    const float* pa = A + (size_t)(row0 + ra) * GK + ca * 4;
    const float* pb = B + (size_t)rb * GN + col0 + cb * 4;
    const int sa0 = ra * 16 + ((ca ^ ((ra >> 1) & 3)) << 2);
    const int sa1 = ra * 16 + (((ca + 1) ^ ((ra >> 1) & 3)) << 2);
    const int sb0 = rb * 128 + ((cb ^ (2 * (rb & 3))) << 2);
    const int sb1 = rb * 128 + (((cb + 1) ^ (2 * (rb & 3))) << 2);
    const uint32_t asb = (uint32_t)__cvta_generic_to_shared(&As[0][0]);
    const uint32_t bsb = (uint32_t)__cvta_generic_to_shared(&Bs[0][0]);

    float c[4][4][4];
#pragma unroll
    for (int i = 0; i < 4; i++)
#pragma unroll
        for (int j = 0; j < 4; j++)
#pragma unroll
            for (int r = 0; r < 4; r++) c[i][j][r] = 0.f;

#define ISSUE(s)                                               \
    {                                                          \
        cp16(asb + ((s)*2048 + sa0) * 4, pa);                  \
        cp16(asb + ((s)*2048 + sa1) * 4, pa + 4);              \
        cp16(bsb + ((s)*2048 + sb0) * 4, pb);                  \
        cp16(bsb + ((s)*2048 + sb1) * 4, pb + 4);              \
        cp_commit();                                           \
        pa += 16;                                              \
        pb += (size_t)16 * GN;                                 \
    }

#define COMPUTE(s)                                                              \
    {                                                                           \
        _Pragma("unroll") for (int ks = 0; ks < 2; ks++) {                      \
            uint32_t a[4][4], b[4][2];                                          \
            _Pragma("unroll") for (int mt = 0; mt < 4; mt++) {                  \
                int m0 = warp_m + mt * 16 + gid;                                \
                int m1 = m0 + 8;                                                \
                a[mt][0] = As[s][m0 * 16 + (((2 * ks) ^ ((m0 >> 1) & 3)) << 2) + tg]; \
                a[mt][1] = As[s][m1 * 16 + (((2 * ks) ^ ((m1 >> 1) & 3)) << 2) + tg]; \
                a[mt][2] = As[s][m0 * 16 + (((2 * ks + 1) ^ ((m0 >> 1) & 3)) << 2) + tg]; \
                a[mt][3] = As[s][m1 * 16 + (((2 * ks + 1) ^ ((m1 >> 1) & 3)) << 2) + tg]; \
            }                                                                   \
            _Pragma("unroll") for (int nt = 0; nt < 4; nt++) {                  \
                int n = warp_n + nt * 8 + gid;                                  \
                int nc = ((n >> 2) ^ (2 * tg)) << 2;                            \
                b[nt][0] = Bs[s][(tg + 8 * ks) * 128 + nc + (n & 3)];           \
                b[nt][1] = Bs[s][(tg + 4 + 8 * ks) * 128 + nc + (n & 3)];       \
            }                                                                   \
            _Pragma("unroll") for (int mt = 0; mt < 4; mt++)                    \
                _Pragma("unroll") for (int nt = 0; nt < 4; nt++)                \
                    mma_tf32(c[mt][nt], a[mt], b[nt][0], b[nt][1]);             \
        }                                                                       \
    }

    ISSUE(0);
    ISSUE(1);

    // 64 k-tiles; stage = t % 3. Main loop t = 0..59 (unrolled x3).
#pragma unroll 1
    for (int t = 0; t < 60; t += 3) {
        cp_wait<1>();
        __syncthreads();
        ISSUE(((t + 2) % 3));
        COMPUTE((0));
        cp_wait<1>();
        __syncthreads();
        ISSUE(((t + 3) % 3));
        COMPUTE((1));
        cp_wait<1>();
        __syncthreads();
        ISSUE(((t + 4) % 3));
        COMPUTE((2));
    }
    // t=60 (stage 0, issue 62->stage 2), t=61 (stage 1, issue 63->stage 0)
    cp_wait<1>();
    __syncthreads();
    ISSUE(2);
    COMPUTE(0);
    cp_wait<1>();
    __syncthreads();
    ISSUE(0);
    COMPUTE(1);
    // t=62 (stage 2), t=63 (stage 0)
    cp_wait<1>();
    __syncthreads();
    COMPUTE(2);
    cp_wait<0>();
    __syncthreads();
    COMPUTE(0);

#pragma unroll
    for (int mt = 0; mt < 4; mt++)
#pragma unroll
        for (int nt = 0; nt < 4; nt++) {
            int row = row0 + warp_m + mt * 16 + gid;
            int col = col0 + warp_n + nt * 8 + tg * 2;
            if (ROUND_C) {
                *(uint2*)&C[(size_t)row * GN + col] =
                    make_uint2(f2tf(c[mt][nt][0]), f2tf(c[mt][nt][1]));
                *(uint2*)&C[(size_t)(row + 8) * GN + col] =
                    make_uint2(f2tf(c[mt][nt][2]), f2tf(c[mt][nt][3]));
            } else {
                *(float2*)&C[(size_t)row * GN + col] =
                    make_float2(c[mt][nt][0], c[mt][nt][1]);
                *(float2*)&C[(size_t)(row + 8) * GN + col] =
                    make_float2(c[mt][nt][2], c[mt][nt][3]);
            }
        }
#undef ISSUE
#undef COMPUTE
}

__global__ __launch_bounds__(256) void gemm_out(const float* __restrict__ A,
                                                const float* __restrict__ B,
                                                float* __restrict__ C) {
    gemm_body<false>(A, B, C, blockIdx.y * 128, blockIdx.x * 128);
}

__global__ __launch_bounds__(256) void gemm_qkv(const float* __restrict__ A,
                                                const float* __restrict__ B0,
                                                const float* __restrict__ B1,
                                                const float* __restrict__ B2,
                                                float* __restrict__ C0,
                                                float* __restrict__ C1,
                                                float* __restrict__ C2) {
    int sel = blockIdx.x >> 3;
    const float* B = (sel == 0) ? B0 : (sel == 1) ? B1 : B2;
    float* C = (sel == 0) ? C0 : (sel == 1) ? C1 : C2;
    gemm_body<true>(A, B, C, blockIdx.y * 128, (blockIdx.x & 7) * 128);
}

// ---------------------------------------------------------------------------
// Tensor-core flash sparse attention. Inputs pre-rounded to tf32 by gemm_qkv;
// loads use raw bits (no cvt). Output rounded to tf32 for the O-projection.
// ---------------------------------------------------------------------------
#define KS_STRIDE 65
#define VS_STRIDE 68
#define PS_STRIDE 72

__global__ __launch_bounds__(128) void attn_mma(const float* __restrict__ Q,
                                                const float* __restrict__ Kg,
                                                const float* __restrict__ Vg,
                                                float* __restrict__ O) {
    __shared__ uint32_t KPs[64 * PS_STRIDE];
    __shared__ uint32_t Vs[64 * VS_STRIDE];

    const int tid = threadIdx.x;
    const int lane = tid & 31;
    const int w = tid >> 5;
    const int gid = lane >> 2;
    const int tg = lane & 3;
    const int wm = w * 16;
    const int q0 = blockIdx.x * 64;
    const int hb = blockIdx.y * HD;
    const unsigned FULL = 0xffffffffu;

    uint32_t qa[8][4];
    {
        const uint32_t* qp = (const uint32_t*)(Q + (size_t)(q0 + wm + gid) * HID + hb);
#pragma unroll
        for (int ks = 0; ks < 8; ks++) {
            qa[ks][0] = qp[ks * 8 + tg];
            qa[ks][1] = qp[8 * HID + ks * 8 + tg];
            qa[ks][2] = qp[ks * 8 + tg + 4];
            qa[ks][3] = qp[8 * HID + ks * 8 + tg + 4];
        }
    }

    float m[2] = {-1e30f, -1e30f}, lsum[2] = {0.f, 0.f};
    float o[8][4];
#pragma unroll
    for (int nt = 0; nt < 8; nt++)
#pragma unroll
        for (int r = 0; r < 4; r++) o[nt][r] = 0.f;

    const int c_start = max(0, q0 - 512);
    const int ng = (c_start + 511) >> 9;
    const int has_pro = (c_start > 0) ? 1 : 0;
    const int nch = ((q0 - c_start) >> 6) + 1 + has_pro;

    for (int ci = 0; ci < nch; ci++) {
        const bool pro = has_pro && (ci == 0);
        const int base = pro ? 0 : c_start + (ci - has_pro) * 64;

#pragma unroll
        for (int l2 = 0; l2 < 8; l2++) {
            int idx = tid + l2 * 128;
            int d4 = idx & 15, kk = idx >> 4;
            int j = pro ? ((kk < ng ? kk : 0) << 9) : (base + kk);
            uint4 kv = *(const uint4*)(Kg + (size_t)j * HID + hb + d4 * 4);
            const uint32_t* kvp = (const uint32_t*)&kv;
#pragma unroll
            for (int u = 0; u < 4; u++)
                KPs[(d4 * 4 + u) * KS_STRIDE + (kk ^ (u << 3))] = kvp[u];
            *(uint4*)&Vs[kk * VS_STRIDE + ((d4 * 4) ^ ((kk & 3) << 3))] =
                *(const uint4*)(Vg + (size_t)j * HID + hb + d4 * 4);
        }
        __syncthreads();

        float s[8][4];
#pragma unroll
        for (int nt = 0; nt < 8; nt++)
#pragma unroll
            for (int r = 0; r < 4; r++) s[nt][r] = 0.f;

#pragma unroll
        for (int ks = 0; ks < 8; ks++) {
            int d0 = tg + 8 * ks, d1 = tg + 4 + 8 * ks;
#pragma unroll
            for (int nt = 0; nt < 8; nt++) {
                int cx = (gid + 8 * nt) ^ (tg << 3);
                uint32_t b0 = KPs[d0 * KS_STRIDE + cx];
                uint32_t b1 = KPs[d1 * KS_STRIDE + cx];
                mma_tf32(s[nt], qa[ks], b0, b1);
            }
        }
        __syncthreads();

#pragma unroll
        for (int r = 0; r < 2; r++) {
            const int i = q0 + wm + gid + 8 * r;
            float rm = -1e30f;
#pragma unroll
            for (int nt = 0; nt < 8; nt++) {
#pragma unroll
                for (int dj = 0; dj < 2; dj++) {
                    int jj = 8 * nt + 2 * tg + dj;
                    bool valid;
                    if (pro) {
                        valid = jj < ng;
                    } else {
                        int j = base + jj;
                        valid = (j <= i) && ((i - j) <= 512 || (j & 511) == 0);
                    }
                    float x = valid ? s[nt][2 * r + dj] * 0.125f : -1e30f;
                    s[nt][2 * r + dj] = x;
                    rm = fmaxf(rm, x);
                }
            }
            rm = fmaxf(rm, __shfl_xor_sync(FULL, rm, 1));
            rm = fmaxf(rm, __shfl_xor_sync(FULL, rm, 2));
            float mn = fmaxf(m[r], rm);
            float scf = __expf(m[r] - mn);
            m[r] = mn;
            float rs = 0.f;
            uint32_t* prow = KPs + (wm + gid + 8 * r) * PS_STRIDE;
#pragma unroll
            for (int nt = 0; nt < 8; nt++) {
                float p0 = __expf(s[nt][2 * r] - mn);
                float p1 = __expf(s[nt][2 * r + 1] - mn);
                rs += p0 + p1;
                *(uint2*)&prow[8 * nt + 2 * tg] = make_uint2(f2tf(p0), f2tf(p1));
                o[nt][2 * r] *= scf;
                o[nt][2 * r + 1] *= scf;
            }
            rs += __shfl_xor_sync(FULL, rs, 1);
            rs += __shfl_xor_sync(FULL, rs, 2);
            lsum[r] = lsum[r] * scf + rs;
        }
        __syncwarp();

        const uint32_t* prow0 = KPs + (wm + gid) * PS_STRIDE;
#pragma unroll
        for (int ks = 0; ks < 8; ks++) {
            uint32_t pa[4];
            pa[0] = prow0[8 * ks + tg];
            pa[1] = prow0[8 * PS_STRIDE + 8 * ks + tg];
            pa[2] = prow0[8 * ks + tg + 4];
            pa[3] = prow0[8 * PS_STRIDE + 8 * ks + tg + 4];
            int j0 = tg + 8 * ks, j1 = tg + 4 + 8 * ks;
#pragma unroll
            for (int nt = 0; nt < 8; nt++) {
                int cx = (gid + 8 * nt) ^ (tg << 3);
                uint32_t vb0 = Vs[j0 * VS_STRIDE + cx];
                uint32_t vb1 = Vs[j1 * VS_STRIDE + cx];
                mma_tf32(o[nt], pa, vb0, vb1);
            }
        }
        __syncthreads();
    }

#pragma unroll
    for (int r = 0; r < 2; r++) {
        float inv = 1.0f / lsum[r];
        float* orow = O + (size_t)(q0 + wm + gid + 8 * r) * HID + hb;
#pragma unroll
        for (int nt = 0; nt < 8; nt++)
            *(uint2*)&orow[8 * nt + 2 * tg] =
                make_uint2(f2tf(o[nt][2 * r] * inv), f2tf(o[nt][2 * r + 1] * inv));
    }
}

// ---------------------------------------------------------------------------
extern "C" void kernel_launch(void* const* d_in, const int* in_sizes, int n_in,
                              void* d_out, int out_size) {
    const float* x   = (const float*)d_in[0];
    const float* w_q = (const float*)d_in[1];
    const float* w_k = (const float*)d_in[2];
    const float* w_v = (const float*)d_in[3];
    const float* w_o = (const float*)d_in[4];
    float* out = (float*)d_out;

    float *q, *k, *v, *att, *xc, *wq, *wk, *wv, *wo;
    cudaGetSymbolAddress((void**)&q, g_q);
    cudaGetSymbolAddress((void**)&k, g_k);
    cudaGetSymbolAddress((void**)&v, g_v);
    cudaGetSymbolAddress((void**)&att, g_att);
    cudaGetSymbolAddress((void**)&xc, g_xc);
    cudaGetSymbolAddress((void**)&wq, g_wq);
    cudaGetSymbolAddress((void**)&wk, g_wk);
    cudaGetSymbolAddress((void**)&wv, g_wv);
    cudaGetSymbolAddress((void**)&wo, g_wo);

    cvt_inputs<<<6144, 256>>>(x, w_q, w_k, w_v, w_o, xc, wq, wk, wv, wo);

    gemm_qkv<<<dim3(24, 16), 256>>>(xc, wq, wk, wv, q, k, v);

    attn_mma<<<dim3(S_LEN / 64, NH), 128>>>(q, k, v, att);

    gemm_out<<<dim3(8, 16), 256>>>(att, wo, out);
}